// round 13
// baseline (speedup 1.0000x reference)
#include <cuda_runtime.h>

// SpikingLayer, R11: R10's bitwise-exact arithmetic, SMSP-correct geometry.
//
// R10 post-mortem (the key finding of this session): fp64 throughput on B300
// is PER-SMSP (~36 cyc/warp-op/SMSP), and SMSP = wid%4 within the block.
// blockDim=32 put every warp on SMSP 0 -> 1/4 of fp64 throughput. Model
// 13.8 warps/SM x ops / n_SMSP x 36 cyc reproduces R2/R9/R10 within 8%.
// Fix: blockDim=128 (4 warps -> 4 SMSPs). ubuf (100-deep u history, doubles)
// becomes 102.4KB dynamic smem; 2 blocks/SM resident = 8 warps, pipe stays
// saturated (demand ~4x supply per SMSP).
//
// Arithmetic (UNCHANGED from R10, which passed with rel_err 7.257581e-4,
// bit-identical to the R2 fp64 orbit):
//   u(t) = fma(Ad, u, c1d)   with c1d selected from the 4 exact doubles
//          {0, 1, -(double)A50f, (double)RN_f32(1-A50f)}  (== R2's cvt'd fmaf)
//   ul(t) == u(t-100) BITWISE (identical fma chain) -- served from smem ubuf
//   w(t) = fma(Bd, w, fma(-E10, ul, u))
//   vm   = exact RN f64->f32 emulated on ALU pipe (underflow->0: flip-safe)
//   spike/refractory: R2's f32 sequence verbatim.
// fp64-pipe ops/thread: 1400 (u 500, inner 400, w 500).

#define SNN_S 65536
#define SNN_T 500
#define SNN_BD 128                             // 4 warps -> all 4 SMSPs
#define SNN_SMEM (100 * SNN_BD * 8)            // 102400 B dynamic smem

// Exact RN f64->f32 on integer pipe (normal f32 range; underflow -> signed 0).
__device__ __forceinline__ float snn_d2f_rn(double w) {
    unsigned long long b   = (unsigned long long)__double_as_longlong(w);
    unsigned long long mag = b & 0x7fffffffffffffffull;
    unsigned int sign = (unsigned int)(b >> 32) & 0x80000000u;
    if (mag < (897ull << 52)) return __uint_as_float(sign);  // |w| < 2^-126
    unsigned long long sh  = mag >> 29;
    unsigned long long rem = mag & 0x1fffffffull;
    sh += (rem > 0x10000000ull) | ((rem == 0x10000000ull) & (sh & 1ull));
    return __uint_as_float((unsigned int)(sh - (896ull << 23)) | sign);
}

__global__ __launch_bounds__(SNN_BD)
void SpikingLayer_90202903151092_kernel(const unsigned* __restrict__ xb,
                                        float* __restrict__ out) {
    extern __shared__ double ubuf[];           // [100][SNN_BD]: slot*SNN_BD + tid
    const int tid = threadIdx.x;
    const int id  = blockIdx.x * SNN_BD + tid; // one neuron per thread

    const double Ad  = 0.81873075307798185867;     // exp(-1/5)
    const double Bd  = 0.90483741803595957316;     // exp(-1/10)
    const double E10 = 4.5399929762484851536e-05;  // exp(-10), f64
    constexpr float A50f = 4.5399929762484851536e-05f;
    const float ALPH = 0.90483741803595957316f;

    // the 4 exact values of (double)fmaf(-A50f, x50, x0), x0,x50 in {0,1}
    constexpr double C00 = 0.0;
    constexpr double C10 = 1.0;
    constexpr double C01 = -(double)A50f;
    constexpr double C11 = (double)((float)(1.0 - (double)A50f));

    double u = 0.0, w = 0.0;
    float  r = 0.0f;
    unsigned long long h0 = 0;                 // bit j = x(t-1-j): lag-50 source
    int slot = 0;                              // t % 100

    const unsigned* xp = xb + id;              // x in {0.0f,1.0f}: bits != 0 iff 1.0f
    float*          op = out + id;

#define SNN_TAIL()                                           \
    {                                                        \
        float vm = snn_d2f_rn(w);                            \
        float vt = vm + r;                                   \
        float s  = (vt >= 1.0f) ? 1.0f : 0.0f;               \
        r = (r - s) * ALPH;                                  \
        op[t * SNN_S] = s;                                   \
        h0 = (h0 << 1) | (unsigned long long)b0;             \
        slot = (slot == 99) ? 0 : slot + 1;                  \
    }

    // Phase A: t in [0,50)
    #pragma unroll 5
    for (int t = 0; t < 50; ++t) {
        int b0 = (xp[t * SNN_S] != 0u);
        u = fma(Ad, u, b0 ? C10 : C00);
        ubuf[slot * SNN_BD + tid] = u;
        w = fma(Bd, w, u);
        SNN_TAIL();
    }

    // Phase B: t in [50,100)
    #pragma unroll 5
    for (int t = 50; t < 100; ++t) {
        int b0  = (xp[t * SNN_S] != 0u);
        int b50 = (int)((h0 >> 49) & 1ull);
        double c1d = b0 ? (b50 ? C11 : C10) : (b50 ? C01 : C00);
        u = fma(Ad, u, c1d);
        ubuf[slot * SNN_BD + tid] = u;
        w = fma(Bd, w, u);
        SNN_TAIL();
    }

    // Phases C+D: t in [100,500) — ul(t) == u(t-100) from the buffer
    #pragma unroll 5
    for (int t = 100; t < SNN_T; ++t) {
        int b0  = (xp[t * SNN_S] != 0u);
        int b50 = (int)((h0 >> 49) & 1ull);
        double c1d = b0 ? (b50 ? C11 : C10) : (b50 ? C01 : C00);
        double ul = ubuf[slot * SNN_BD + tid]; // u(t-100), read before overwrite
        u = fma(Ad, u, c1d);
        ubuf[slot * SNN_BD + tid] = u;
        w = fma(Bd, w, fma(-E10, ul, u));
        SNN_TAIL();
    }
#undef SNN_TAIL
}

extern "C" void kernel_launch(void* const* d_in, const int* in_sizes, int n_in,
                              void* d_out, int out_size) {
    const unsigned* xb = (const unsigned*)d_in[0];  // binary_input (T,B,1,N) as bits
    // d_in[1] = epsp_kernel (1,149): algebraically folded into the recurrence
    float* out = (float*)d_out;                     // spikes (T,B,N) float32
    cudaFuncSetAttribute(SpikingLayer_90202903151092_kernel,
                         cudaFuncAttributeMaxDynamicSharedMemorySize, SNN_SMEM);
    // 65536 / 128 = 512 blocks; 4 warps/block span all 4 SMSPs
    SpikingLayer_90202903151092_kernel<<<512, SNN_BD, SNN_SMEM>>>(xb, out);
}

// round 15
// speedup vs baseline: 1.1208x; 1.1208x over previous
#include <cuda_runtime.h>

// SpikingLayer, R12: R9 verbatim, with ONLY the F2F f64->f32 replaced by the
// integer-pipe RN emulation (bitwise-proven in R10/R11: rel_err unchanged).
//
// R11 post-mortem: per-SMSP fp64 theory falsified (blockDim 32 vs 128 at same
// 8 warps/SM: identical dur). R10/R11 carried three confounded changes
// (smem ubuf, d2f, halved occupancy) and regressed vs R9. This round is a
// controlled bisection: R9 structure, geometry, loads, register ul chain, and
// 16 warps/SM all UNCHANGED; fp64-pipe ops 2300 -> 1800 by removing the 500
// F2F ops. R2->R9 established cvts price like DFMAs (~0.123us/op removed),
// so predicted ~245us; a neutral or 350us outcome instead isolates the
// remaining unknown (F2F-free vs d2f-poison).
//
// Orbit is BIT-IDENTICAL to R2's fp64 kernel (7.257581e-4):
//   c1d/c2d selected from the 4 exact doubles {0, 1, -(double)A50f,
//   (double)RN_f32(1-A50f)} == (double)fmaf(-A50f,x50,x0) on binary x;
//   u/ul/w fma sequence verbatim; d2f is exact RN (underflow->0 flip-safe);
//   spike/refractory f32 sequence verbatim.

#define SNN_S 65536
#define SNN_T 500

// Exact RN f64->f32 on integer pipe (normal f32 range; underflow -> signed 0).
__device__ __forceinline__ float snn_d2f_rn(double w) {
    unsigned long long b   = (unsigned long long)__double_as_longlong(w);
    unsigned long long mag = b & 0x7fffffffffffffffull;
    unsigned int sign = (unsigned int)(b >> 32) & 0x80000000u;
    if (mag < (897ull << 52)) return __uint_as_float(sign);  // |w| < 2^-126
    unsigned long long sh  = mag >> 29;
    unsigned long long rem = mag & 0x1fffffffull;
    sh += (rem > 0x10000000ull) | ((rem == 0x10000000ull) & (sh & 1ull));
    return __uint_as_float((unsigned int)(sh - (896ull << 23)) | sign);
}

__global__ __launch_bounds__(64, 8)
void SpikingLayer_90202903151092_kernel(const float* __restrict__ x,
                                        float* __restrict__ out) {
    const int id = blockIdx.x * 64 + threadIdx.x;   // one neuron per thread

    const double Ad   = 0.81873075307798185867;      // exp(-1/5)
    const double Bd   = 0.90483741803595957316;      // exp(-1/10)
    const double E10  = 4.5399929762484851536e-05;   // exp(-10), f64
    constexpr float  A50f = 4.5399929762484851536e-05f; // exp(-10), f32
    const float  ALPH = 0.90483741803595957316f;     // refractory decay (f32)

    // The 4 exact values of (double)fmaf(-A50f, x50, x0), x0,x50 in {0,1}:
    constexpr double C00 = 0.0;
    constexpr double C10 = 1.0;                       // x0=1, x50=0
    constexpr double C01 = -(double)A50f;             // x0=0, x50=1
    constexpr double C11 = (double)((float)(1.0 - (double)A50f)); // x0=1, x50=1

    double u = 0.0, ul = 0.0, w = 0.0;
    float  r = 0.0f;

    const float* xp = x + id;
    float*       op = out + id;

    // Phase A: t in [0,50) — no delayed terms
    #pragma unroll 5
    for (int t = 0; t < 50; ++t) {
        bool b0 = (xp[(long)t * SNN_S] != 0.0f);
        double c1d = b0 ? C10 : C00;                 // == (double)x0
        u = fma(Ad, u, c1d);
        w = fma(Bd, w, u);
        float vt = snn_d2f_rn(w) + r;
        float s  = (vt >= 1.0f) ? 1.0f : 0.0f;
        r = (r - s) * ALPH;
        op[(long)t * SNN_S] = s;
    }

    // Phase B: t in [50,100) — x(t-50) active
    #pragma unroll 5
    for (int t = 50; t < 100; ++t) {
        bool b0  = (xp[(long)t * SNN_S] != 0.0f);
        bool b50 = (xp[(long)(t - 50) * SNN_S] != 0.0f);
        double c1d = b0 ? (b50 ? C11 : C10) : (b50 ? C01 : C00);
        u = fma(Ad, u, c1d);
        w = fma(Bd, w, u);
        float vt = snn_d2f_rn(w) + r;
        float s  = (vt >= 1.0f) ? 1.0f : 0.0f;
        r = (r - s) * ALPH;
        op[(long)t * SNN_S] = s;
    }

    // Phase C: t in [100,150) — x(t-100) active (lagged u starts)
    #pragma unroll 5
    for (int t = 100; t < 150; ++t) {
        bool b0   = (xp[(long)t * SNN_S] != 0.0f);
        bool b50  = (xp[(long)(t - 50) * SNN_S] != 0.0f);
        bool b100 = (xp[(long)(t - 100) * SNN_S] != 0.0f);
        double c1d = b0 ? (b50 ? C11 : C10) : (b50 ? C01 : C00);
        double c2d = b100 ? C10 : C00;               // == (double)x100
        u  = fma(Ad, u,  c1d);
        ul = fma(Ad, ul, c2d);
        w  = fma(Bd, w, fma(-E10, ul, u));
        float vt = snn_d2f_rn(w) + r;
        float s  = (vt >= 1.0f) ? 1.0f : 0.0f;
        r = (r - s) * ALPH;
        op[(long)t * SNN_S] = s;
    }

    // Phase D: t in [150,500) — steady state
    #pragma unroll 5
    for (int t = 150; t < SNN_T; ++t) {
        bool b0   = (xp[(long)t * SNN_S] != 0.0f);
        bool b50  = (xp[(long)(t - 50) * SNN_S] != 0.0f);
        bool b100 = (xp[(long)(t - 100) * SNN_S] != 0.0f);
        bool b150 = (xp[(long)(t - 150) * SNN_S] != 0.0f);
        double c1d = b0   ? (b50  ? C11 : C10) : (b50  ? C01 : C00);
        double c2d = b100 ? (b150 ? C11 : C10) : (b150 ? C01 : C00);
        u  = fma(Ad, u,  c1d);
        ul = fma(Ad, ul, c2d);
        w  = fma(Bd, w, fma(-E10, ul, u));
        float vt = snn_d2f_rn(w) + r;
        float s  = (vt >= 1.0f) ? 1.0f : 0.0f;
        r = (r - s) * ALPH;
        op[(long)t * SNN_S] = s;
    }
}

extern "C" void kernel_launch(void* const* d_in, const int* in_sizes, int n_in,
                              void* d_out, int out_size) {
    const float* x = (const float*)d_in[0];   // binary_input (T,B,1,N) float32
    // d_in[1] = epsp_kernel (1,149): algebraically folded into the recurrence
    float* out = (float*)d_out;               // spikes (T,B,N) float32
    SpikingLayer_90202903151092_kernel<<<1024, 64>>>(x, out);
}